// round 6
// baseline (speedup 1.0000x reference)
#include <cuda_runtime.h>
#include <cstdint>

// VecArrayMultiplier54x54: the {0,1} gate network is exact, so
// out[row] = bits of (uint54(A[row]) * uint54(B[row])), LSB first, as 0/1 floats.
//
// R6: 8 rows per warp (32 front-batched independent LDG.32 per thread-slot,
// < 55-outstanding cap) to amortize L2-hit latency in the warm graph-replay
// loop. 1024 warps in 256 CTAs x 128 threads -> all 148 SMs covered.
// Epilogue per row: 4 ballots -> 64x64->128 IMAD -> lane<27 STG.128 of
// bit-pattern floats (bit * 0x3F800000, no I2F).

#define ROWS_PER_WARP 8

__global__ void __launch_bounds__(128)
mul54x54_mlp8_kernel(const float* __restrict__ A,
                     const float* __restrict__ B,
                     float* __restrict__ out,
                     int batch) {
    const int gwarp = (int)((blockIdx.x * blockDim.x + threadIdx.x) >> 5);
    const int lane  = threadIdx.x & 31;
    const int nwarps = (int)(gridDim.x * blockDim.x) >> 5;

    int rows[ROWS_PER_WARP];
    float av0[ROWS_PER_WARP], bv0[ROWS_PER_WARP];
    float av1[ROWS_PER_WARP], bv1[ROWS_PER_WARP];

    const bool tail = (lane < 22);

    // Front-batched loads: 32 independent LDG.32 before any dependency.
    #pragma unroll
    for (int i = 0; i < ROWS_PER_WARP; i++) {
        int row = gwarp + i * nwarps;
        rows[i] = row;
        av1[i] = 0.0f; bv1[i] = 0.0f;
        if (row < batch) {
            const float* __restrict__ a_row = A + (size_t)row * 54;
            const float* __restrict__ b_row = B + (size_t)row * 54;
            av0[i] = a_row[lane];
            bv0[i] = b_row[lane];
            if (tail) {
                av1[i] = a_row[32 + lane];
                bv1[i] = b_row[32 + lane];
            }
        } else {
            av0[i] = 0.0f; bv0[i] = 0.0f;
        }
    }

    #pragma unroll
    for (int i = 0; i < ROWS_PER_WARP; i++) {
        unsigned ma0 = __ballot_sync(0xFFFFFFFFu, av0[i] > 0.5f);
        unsigned ma1 = __ballot_sync(0xFFFFFFFFu, av1[i] > 0.5f);
        unsigned mb0 = __ballot_sync(0xFFFFFFFFu, bv0[i] > 0.5f);
        unsigned mb1 = __ballot_sync(0xFFFFFFFFu, bv1[i] > 0.5f);

        const uint64_t a = (uint64_t)ma0 | ((uint64_t)(ma1 & 0x3FFFFFu) << 32);
        const uint64_t b = (uint64_t)mb0 | ((uint64_t)(mb1 & 0x3FFFFFu) << 32);

        const uint64_t lo = a * b;             // product bits [0:64)
        const uint64_t hi = __umul64hi(a, b);  // product bits [64:108)

        if (lane < 27 && rows[i] < batch) {
            unsigned nib = (lane < 16) ? (unsigned)(lo >> (lane * 4))
                                       : (unsigned)(hi >> ((lane - 16) * 4));
            uint4 v;
            v.x = ( nib        & 1u) * 0x3F800000u;
            v.y = ((nib >> 1)  & 1u) * 0x3F800000u;
            v.z = ((nib >> 2)  & 1u) * 0x3F800000u;
            v.w = ((nib >> 3)  & 1u) * 0x3F800000u;
            ((uint4*)(out + (size_t)rows[i] * 108))[lane] = v;
        }
    }
}

extern "C" void kernel_launch(void* const* d_in, const int* in_sizes, int n_in,
                              void* d_out, int out_size) {
    const float* A = (const float*)d_in[0];
    const float* B = (const float*)d_in[1];
    float* out = (float*)d_out;

    const int batch = in_sizes[0] / 54;                                   // 8192
    const int threads = 128;                                              // 4 warps/CTA
    const int warpsNeeded = (batch + ROWS_PER_WARP - 1) / ROWS_PER_WARP;  // 1024
    const int blocks = (warpsNeeded + 3) / 4;                             // 256 CTAs

    mul54x54_mlp8_kernel<<<blocks, threads>>>(A, B, out, batch);
}

// round 7
// speedup vs baseline: 1.3037x; 1.3037x over previous
#include <cuda_runtime.h>
#include <cstdint>

// VecArrayMultiplier54x54: the {0,1} gate network is exact, so
// out[row] = bits of (uint54(A[row]) * uint54(B[row])), LSB first, as 0/1 floats.
//
// R7: R5's winning shape (2048 warps, 4 rows/warp, 16 front-batched LDG.32)
// with better geometry (512 CTAs x 128 threads for smooth wave balance on
// 148 SMs) and a guard-free fast path when batch == nwarps*4 (8192 case).
// Epilogue per row: 4 ballots -> 64x64->128 IMAD -> lane<27 STG.128 of
// bit-pattern floats (bit * 0x3F800000, no I2F).

#define ROWS_PER_WARP 4

template<bool EXACT>
__global__ void __launch_bounds__(128)
mul54x54_r7_kernel(const float* __restrict__ A,
                   const float* __restrict__ B,
                   float* __restrict__ out,
                   int batch) {
    const int gwarp = (int)((blockIdx.x * blockDim.x + threadIdx.x) >> 5);
    const int lane  = threadIdx.x & 31;
    const int nwarps = (int)(gridDim.x * blockDim.x) >> 5;

    float av0[ROWS_PER_WARP], bv0[ROWS_PER_WARP];
    float av1[ROWS_PER_WARP], bv1[ROWS_PER_WARP];

    const bool tail = (lane < 22);

    // Front-batched loads: 16 independent LDG.32 before any dependency.
    #pragma unroll
    for (int i = 0; i < ROWS_PER_WARP; i++) {
        const int row = gwarp + i * nwarps;
        av1[i] = 0.0f; bv1[i] = 0.0f;
        if (EXACT || row < batch) {
            const float* __restrict__ a_row = A + (size_t)row * 54;
            const float* __restrict__ b_row = B + (size_t)row * 54;
            av0[i] = a_row[lane];
            bv0[i] = b_row[lane];
            if (tail) {
                av1[i] = a_row[32 + lane];
                bv1[i] = b_row[32 + lane];
            }
        } else {
            av0[i] = 0.0f; bv0[i] = 0.0f;
        }
    }

    #pragma unroll
    for (int i = 0; i < ROWS_PER_WARP; i++) {
        unsigned ma0 = __ballot_sync(0xFFFFFFFFu, av0[i] > 0.5f);
        unsigned ma1 = __ballot_sync(0xFFFFFFFFu, av1[i] > 0.5f);
        unsigned mb0 = __ballot_sync(0xFFFFFFFFu, bv0[i] > 0.5f);
        unsigned mb1 = __ballot_sync(0xFFFFFFFFu, bv1[i] > 0.5f);

        const uint64_t a = (uint64_t)ma0 | ((uint64_t)(ma1 & 0x3FFFFFu) << 32);
        const uint64_t b = (uint64_t)mb0 | ((uint64_t)(mb1 & 0x3FFFFFu) << 32);

        const uint64_t lo = a * b;             // product bits [0:64)
        const uint64_t hi = __umul64hi(a, b);  // product bits [64:108)

        const int row = gwarp + i * nwarps;
        if (lane < 27 && (EXACT || row < batch)) {
            unsigned nib = (lane < 16) ? (unsigned)(lo >> (lane * 4))
                                       : (unsigned)(hi >> ((lane - 16) * 4));
            uint4 v;
            v.x = ( nib        & 1u) * 0x3F800000u;
            v.y = ((nib >> 1)  & 1u) * 0x3F800000u;
            v.z = ((nib >> 2)  & 1u) * 0x3F800000u;
            v.w = ((nib >> 3)  & 1u) * 0x3F800000u;
            ((uint4*)(out + (size_t)row * 108))[lane] = v;
        }
    }
}

extern "C" void kernel_launch(void* const* d_in, const int* in_sizes, int n_in,
                              void* d_out, int out_size) {
    const float* A = (const float*)d_in[0];
    const float* B = (const float*)d_in[1];
    float* out = (float*)d_out;

    const int batch = in_sizes[0] / 54;                                   // 8192
    const int threads = 128;                                              // 4 warps/CTA
    const int warpsNeeded = (batch + ROWS_PER_WARP - 1) / ROWS_PER_WARP;  // 2048
    const int blocks = (warpsNeeded + 3) / 4;                             // 512 CTAs

    const int totalWarps = blocks * (threads / 32);
    if (totalWarps * ROWS_PER_WARP == batch) {
        mul54x54_r7_kernel<true><<<blocks, threads>>>(A, B, out, batch);
    } else {
        mul54x54_r7_kernel<false><<<blocks, threads>>>(A, B, out, batch);
    }
}

// round 8
// speedup vs baseline: 1.3413x; 1.0288x over previous
#include <cuda_runtime.h>
#include <cstdint>

// VecArrayMultiplier54x54: the {0,1} gate network is exact, so
// out[row] = bits of (uint54(A[row]) * uint54(B[row])), LSB first, as 0/1 floats.
//
// R8 = R5's winning shape (4 rows/warp, 16 front-batched LDG.32, 256-thread
// CTAs) with a perfectly balanced wave: 304 CTAs = exactly 2 per SM on
// GB300's 152 SMs (2432 warps; warps 896+ do 3 rows via the row<batch guard).
// Epilogue per row: 4 ballots -> 64x64->128 IMAD -> lane<27 STG.128 of
// bit-pattern floats (bit * 0x3F800000, no I2F).

#define ROWS_PER_WARP 4

__global__ void __launch_bounds__(256)
mul54x54_r8_kernel(const float* __restrict__ A,
                   const float* __restrict__ B,
                   float* __restrict__ out,
                   int batch) {
    const int gwarp = (int)((blockIdx.x * blockDim.x + threadIdx.x) >> 5);
    const int lane  = threadIdx.x & 31;
    const int nwarps = (int)(gridDim.x * blockDim.x) >> 5;

    float av0[ROWS_PER_WARP], bv0[ROWS_PER_WARP];
    float av1[ROWS_PER_WARP], bv1[ROWS_PER_WARP];

    const bool tail = (lane < 22);

    // Front-batched loads: up to 16 independent LDG.32 before any dependency.
    #pragma unroll
    for (int i = 0; i < ROWS_PER_WARP; i++) {
        const int row = gwarp + i * nwarps;
        av1[i] = 0.0f; bv1[i] = 0.0f;
        if (row < batch) {
            const float* __restrict__ a_row = A + (size_t)row * 54;
            const float* __restrict__ b_row = B + (size_t)row * 54;
            av0[i] = a_row[lane];
            bv0[i] = b_row[lane];
            if (tail) {
                av1[i] = a_row[32 + lane];
                bv1[i] = b_row[32 + lane];
            }
        } else {
            av0[i] = 0.0f; bv0[i] = 0.0f;
        }
    }

    #pragma unroll
    for (int i = 0; i < ROWS_PER_WARP; i++) {
        unsigned ma0 = __ballot_sync(0xFFFFFFFFu, av0[i] > 0.5f);
        unsigned ma1 = __ballot_sync(0xFFFFFFFFu, av1[i] > 0.5f);
        unsigned mb0 = __ballot_sync(0xFFFFFFFFu, bv0[i] > 0.5f);
        unsigned mb1 = __ballot_sync(0xFFFFFFFFu, bv1[i] > 0.5f);

        const uint64_t a = (uint64_t)ma0 | ((uint64_t)(ma1 & 0x3FFFFFu) << 32);
        const uint64_t b = (uint64_t)mb0 | ((uint64_t)(mb1 & 0x3FFFFFu) << 32);

        const uint64_t lo = a * b;             // product bits [0:64)
        const uint64_t hi = __umul64hi(a, b);  // product bits [64:108)

        const int row = gwarp + i * nwarps;
        if (lane < 27 && row < batch) {
            unsigned nib = (lane < 16) ? (unsigned)(lo >> (lane * 4))
                                       : (unsigned)(hi >> ((lane - 16) * 4));
            uint4 v;
            v.x = ( nib        & 1u) * 0x3F800000u;
            v.y = ((nib >> 1)  & 1u) * 0x3F800000u;
            v.z = ((nib >> 2)  & 1u) * 0x3F800000u;
            v.w = ((nib >> 3)  & 1u) * 0x3F800000u;
            ((uint4*)(out + (size_t)row * 108))[lane] = v;
        }
    }
}

extern "C" void kernel_launch(void* const* d_in, const int* in_sizes, int n_in,
                              void* d_out, int out_size) {
    const float* A = (const float*)d_in[0];
    const float* B = (const float*)d_in[1];
    float* out = (float*)d_out;

    const int batch = in_sizes[0] / 54;   // 8192 expected
    const int threads = 256;              // 8 warps/CTA

    // GB300: 152 SMs -> 2 CTAs/SM = 304 CTAs (2432 warps, ~3.4 rows/warp).
    // Never launch more warps than rows (each warp must get >=1 row at i=0... 
    // guard covers it regardless), and cover batch fully.
    int blocks = 304;
    const int warpsPerBlock = threads / 32;
    const int minBlocks = (batch + ROWS_PER_WARP * warpsPerBlock - 1) /
                          (ROWS_PER_WARP * warpsPerBlock);
    if (blocks < minBlocks) blocks = minBlocks;          // tiny-batch safety
    const int maxBlocks = (batch + warpsPerBlock - 1) / warpsPerBlock;
    if (blocks > maxBlocks) blocks = maxBlocks;          // avoid fully idle warps

    mul54x54_r8_kernel<<<blocks, threads>>>(A, B, out, batch);
}

// round 9
// speedup vs baseline: 1.3478x; 1.0048x over previous
#include <cuda_runtime.h>
#include <cstdint>

// VecArrayMultiplier54x54: the {0,1} gate network is exact, so
// out[row] = bits of (uint54(A[row]) * uint54(B[row])), LSB first, as 0/1 floats.
//
// R9 = R5's winning shape (2048 warps, 4 rows/warp, 16 front-batched LDG.32,
// 256 CTAs x 256 threads) specialized at compile time:
//   - NWARPS is a template constant -> row stride i*NWARPS*54 folds into
//     constant load/store offsets (no per-row address IMADs)
//   - guard-free (batch == NWARPS*ROWS exactly for 8192)
// Epilogue per row: 4 ballots -> 64x64->128 IMAD -> lane<27 STG.128 of
// bit-pattern floats (bit * 0x3F800000, no I2F).

#define ROWS_PER_WARP 4

template<int NWARPS>
__global__ void __launch_bounds__(256)
mul54x54_r9_kernel(const float* __restrict__ A,
                   const float* __restrict__ B,
                   float* __restrict__ out) {
    const int gwarp = (int)((blockIdx.x * blockDim.x + threadIdx.x) >> 5);
    const int lane  = threadIdx.x & 31;

    const float* __restrict__ a0 = A + (size_t)gwarp * 54;
    const float* __restrict__ b0 = B + (size_t)gwarp * 54;

    float av0[ROWS_PER_WARP], bv0[ROWS_PER_WARP];
    float av1[ROWS_PER_WARP], bv1[ROWS_PER_WARP];

    const bool tail = (lane < 22);

    // 16 independent LDG.32, constant offsets i*NWARPS*54 from one base.
    #pragma unroll
    for (int i = 0; i < ROWS_PER_WARP; i++) {
        const size_t off = (size_t)i * NWARPS * 54;
        av0[i] = a0[off + lane];
        bv0[i] = b0[off + lane];
        av1[i] = 0.0f; bv1[i] = 0.0f;
        if (tail) {
            av1[i] = a0[off + 32 + lane];
            bv1[i] = b0[off + 32 + lane];
        }
    }

    #pragma unroll
    for (int i = 0; i < ROWS_PER_WARP; i++) {
        unsigned ma0 = __ballot_sync(0xFFFFFFFFu, av0[i] > 0.5f);
        unsigned ma1 = __ballot_sync(0xFFFFFFFFu, av1[i] > 0.5f);
        unsigned mb0 = __ballot_sync(0xFFFFFFFFu, bv0[i] > 0.5f);
        unsigned mb1 = __ballot_sync(0xFFFFFFFFu, bv1[i] > 0.5f);

        const uint64_t a = (uint64_t)ma0 | ((uint64_t)(ma1 & 0x3FFFFFu) << 32);
        const uint64_t b = (uint64_t)mb0 | ((uint64_t)(mb1 & 0x3FFFFFu) << 32);

        const uint64_t lo = a * b;             // product bits [0:64)
        const uint64_t hi = __umul64hi(a, b);  // product bits [64:108)

        if (lane < 27) {
            unsigned nib = (lane < 16) ? (unsigned)(lo >> (lane * 4))
                                       : (unsigned)(hi >> ((lane - 16) * 4));
            uint4 v;
            v.x = ( nib        & 1u) * 0x3F800000u;
            v.y = ((nib >> 1)  & 1u) * 0x3F800000u;
            v.z = ((nib >> 2)  & 1u) * 0x3F800000u;
            v.w = ((nib >> 3)  & 1u) * 0x3F800000u;
            ((uint4*)(out + ((size_t)gwarp + (size_t)i * NWARPS) * 108))[lane] = v;
        }
    }
}

// Generic fallback for unexpected batch sizes.
__global__ void __launch_bounds__(256)
mul54x54_generic_kernel(const float* __restrict__ A,
                        const float* __restrict__ B,
                        float* __restrict__ out,
                        int batch) {
    const int row  = (int)((blockIdx.x * blockDim.x + threadIdx.x) >> 5);
    const int lane = threadIdx.x & 31;
    if (row >= batch) return;

    const float* __restrict__ a_row = A + (size_t)row * 54;
    const float* __restrict__ b_row = B + (size_t)row * 54;

    float av0 = a_row[lane], bv0 = b_row[lane];
    float av1 = 0.0f, bv1 = 0.0f;
    if (lane < 22) { av1 = a_row[32 + lane]; bv1 = b_row[32 + lane]; }

    unsigned ma0 = __ballot_sync(0xFFFFFFFFu, av0 > 0.5f);
    unsigned ma1 = __ballot_sync(0xFFFFFFFFu, av1 > 0.5f);
    unsigned mb0 = __ballot_sync(0xFFFFFFFFu, bv0 > 0.5f);
    unsigned mb1 = __ballot_sync(0xFFFFFFFFu, bv1 > 0.5f);

    const uint64_t a = (uint64_t)ma0 | ((uint64_t)(ma1 & 0x3FFFFFu) << 32);
    const uint64_t b = (uint64_t)mb0 | ((uint64_t)(mb1 & 0x3FFFFFu) << 32);
    const uint64_t lo = a * b;
    const uint64_t hi = __umul64hi(a, b);

    if (lane < 27) {
        unsigned nib = (lane < 16) ? (unsigned)(lo >> (lane * 4))
                                   : (unsigned)(hi >> ((lane - 16) * 4));
        uint4 v;
        v.x = ( nib        & 1u) * 0x3F800000u;
        v.y = ((nib >> 1)  & 1u) * 0x3F800000u;
        v.z = ((nib >> 2)  & 1u) * 0x3F800000u;
        v.w = ((nib >> 3)  & 1u) * 0x3F800000u;
        ((uint4*)(out + (size_t)row * 108))[lane] = v;
    }
}

extern "C" void kernel_launch(void* const* d_in, const int* in_sizes, int n_in,
                              void* d_out, int out_size) {
    const float* A = (const float*)d_in[0];
    const float* B = (const float*)d_in[1];
    float* out = (float*)d_out;

    const int batch = in_sizes[0] / 54;     // 8192 expected
    constexpr int NWARPS = 2048;            // 256 CTAs x 256 threads

    if (batch == NWARPS * ROWS_PER_WARP) {
        mul54x54_r9_kernel<NWARPS><<<256, 256>>>(A, B, out);
    } else {
        const int blocks = (batch + 7) / 8; // 1 row/warp fallback
        mul54x54_generic_kernel<<<blocks, 256>>>(A, B, out, batch);
    }
}